// round 8
// baseline (speedup 1.0000x reference)
#include <cuda_runtime.h>

// ElevationLoss: tversky(logits, gt) * elevation(softmax, heights, gt)
// B=8, C=2, H=W=512, gt in {0,1}. Persistent-grid fused kernel:
// grid-stride over 4x2 pixel tiles, SoA partials, coalesced last-block tail.

#define IMG_H 512
#define IMG_W 512
#define HW (IMG_H * IMG_W)        // 262144
#define NBATCH 8
#define NPIX (NBATCH * HW)        // 2097152
#define NTILES (NPIX / 8)         // 262144 tiles (4 wide x 2 tall)
#define NT 128
#define NBLK 592                  // 4 blocks per SM on 148 SMs
#define NACC 5

// SoA per-block partials: [Σp1, inter1, count1, comb_sum, ud_sum]
__device__ float g_part5[NACC][NBLK];
__device__ unsigned g_count = 0;               // reset by last block each launch
__device__ __align__(16) float g_zrowf[IMG_W]; // zero-initialized, never written
__device__ __align__(16) int   g_zrowi[IMG_W]; // zero-initialized, never written

__device__ __forceinline__ float block_reduce(float v, float* sh) {
    #pragma unroll
    for (int o = 16; o > 0; o >>= 1) v += __shfl_down_sync(0xffffffffu, v, o);
    int lane = threadIdx.x & 31;
    int w = threadIdx.x >> 5;
    __syncthreads();                 // protect sh reuse across calls
    if (lane == 0) sh[w] = v;
    __syncthreads();
    if (w == 0) {
        v = (lane < NT / 32) ? sh[lane] : 0.0f;
        #pragma unroll
        for (int o = NT / 64; o > 0; o >>= 1)
            v += __shfl_down_sync(0xffffffffu, v, o);
    }
    return v;   // valid in thread 0
}

__global__ __launch_bounds__(NT) void elev_fused(
    const float* __restrict__ pred,   // (B,2,H,W)
    const float* __restrict__ hgt,    // (B,1,H,W)
    const int*   __restrict__ gt,     // (B,1,H,W)
    float* __restrict__ out)
{
    float s_p1 = 0.f, s_i1 = 0.f, s_ud = 0.f;
    int cbi = 0, c1i = 0;

    for (int tile = blockIdx.x * NT + threadIdx.x; tile < NTILES;
         tile += NBLK * NT) {
        int b  = tile >> 15;       // 32768 tiles per image
        int r  = tile & 32767;
        int ty = r >> 7;           // 256 tile-rows
        int xg = r & 127;          // 128 tiles per row
        int x0 = xg << 2;
        int y0 = ty << 1;

        const float* pb = pred + ((size_t)b * 2) * HW;
        const float* hb = hgt + (size_t)b * HW;
        const int*   gb = gt  + (size_t)b * HW;

        // Row pointers: OOB rows -> static zero row (reference zero padding).
        const float* hr[4];
        const int*   gr[4];
        #pragma unroll
        for (int k = 0; k < 4; k++) {
            int ry = y0 - 1 + k;
            bool v = (unsigned)ry < (unsigned)IMG_H;
            hr[k] = v ? (hb + (ry << 9)) : g_zrowf;
            gr[k] = v ? (gb + (ry << 9)) : g_zrowi;
        }
        bool lv = (x0 > 0);
        bool rv = (x0 + 4 < IMG_W);
        int  xl = lv ? x0 - 1 : 0;
        int  xr = rv ? x0 + 4 : IMG_W - 1;

        // ---------- front-batched loads (all independent) ----------
        float4 l0a = ((const float4*)pb)[( y0      << 7) + xg];
        float4 l1a = ((const float4*)pb)[(HW >> 2) + (( y0      ) << 7) + xg];
        float4 l0b = ((const float4*)pb)[((y0 + 1) << 7) + xg];
        float4 l1b = ((const float4*)pb)[(HW >> 2) + ((y0 + 1) << 7) + xg];

        int4   gv[4];  float4 hv[4];
        int    gl[4],  grt[4];
        float  hl[4],  hrt[4];
        #pragma unroll
        for (int k = 0; k < 4; k++) {
            gv[k]  = ((const int4*)  gr[k])[xg];
            hv[k]  = ((const float4*)hr[k])[xg];
            gl[k]  = gr[k][xl];  hl[k]  = hr[k][xl];
            grt[k] = gr[k][xr];  hrt[k] = hr[k][xr];
        }
        #pragma unroll
        for (int k = 0; k < 4; k++) {       // edge validity (predicated selects)
            gl[k]  = lv ? gl[k]  : 0;  hl[k]  = lv ? hl[k]  : 0.f;
            grt[k] = rv ? grt[k] : 0;  hrt[k] = rv ? hrt[k] : 0.f;
        }

        // ---------- centers ----------
        float hc[8] = {hv[1].x, hv[1].y, hv[1].z, hv[1].w,
                       hv[2].x, hv[2].y, hv[2].z, hv[2].w};
        unsigned flm =
            (unsigned)gv[1].x | ((unsigned)gv[1].y << 1) |
            ((unsigned)gv[1].z << 2) | ((unsigned)gv[1].w << 3) |
            ((unsigned)gv[2].x << 4) | ((unsigned)gv[2].y << 5) |
            ((unsigned)gv[2].z << 6) | ((unsigned)gv[2].w << 7);
        c1i += __popc(flm);

        // ---------- softmax + unified pred + tversky prob partials ----------
        float u[8];
        {
            float t[8] = {l1a.x - l0a.x, l1a.y - l0a.y, l1a.z - l0a.z, l1a.w - l0a.w,
                          l1b.x - l0b.x, l1b.y - l0b.y, l1b.z - l0b.z, l1b.w - l0b.w};
            #pragma unroll
            for (int p = 0; p < 8; p++) {
                float p1 = 1.0f / (1.0f + __expf(-t[p]));
                s_p1 += p1;
                if ((flm >> p) & 1u) s_i1 += p1;
                u[p] = (t[p] > 0.f) ? p1 : p1 - 1.f;
            }
        }

        // ---------- stencil ----------
        // enc = (1<<16) + (1 - nsi), nsi = 2g-1 = -gt_sign; hw = -nsi*h.
        // pair: m = fma(nsi, hc, hw) = gt_sign*(h-hc); pass iff m <= 0.
        // Pass adds enc: hi16 += 1 (cb), lo16 += 1 - nsi (cb + dd).
        int   acc[8] = {0,0,0,0,0,0,0,0};
        int   enc[6];
        float sg[6], hw[6];

        auto build = [&](int k) {
            int   gg[6] = {gl[k], gv[k].x, gv[k].y, gv[k].z, gv[k].w, grt[k]};
            float hh[6] = {hl[k], hv[k].x, hv[k].y, hv[k].z, hv[k].w, hrt[k]};
            #pragma unroll
            for (int j = 0; j < 6; j++) {
                int nsi = 2 * gg[j] - 1;
                enc[j] = 65537 - nsi;
                sg[j]  = (float)nsi;
                hw[j]  = -sg[j] * hh[j];
            }
        };
        auto sten = [&](int pr) {
            #pragma unroll
            for (int px = 0; px < 4; px++) {
                #pragma unroll
                for (int dx = 0; dx < 3; dx++) {
                    int j = px + dx;
                    float m = fmaf(sg[j], hc[pr + px], hw[j]);
                    if (m <= 0.f) acc[pr + px] += enc[j];
                }
            }
        };

        build(1); sten(0); sten(4);      // row y0   -> both pixel rows
        build(2); sten(0); sten(4);      // row y0+1 -> both pixel rows
        build(0); sten(0);               // row y0-1 -> pixel row 0
        build(3); sten(4);               // row y0+2 -> pixel row 1

        #pragma unroll
        for (int p = 0; p < 8; p++) {
            int cb = acc[p] >> 16;
            int dd = (acc[p] & 0xFFFF) - cb;
            cbi += cb;
            s_ud = fmaf(u[p], (float)dd, s_ud);
        }
    }

    // ---- per-block reduction (SoA partials) ----
    __shared__ float sh[NT / 32];
    {
        float acc[NACC] = {s_p1, s_i1, (float)c1i, (float)cbi, s_ud};
        #pragma unroll
        for (int k = 0; k < NACC; k++) {
            float r = block_reduce(acc[k], sh);
            if (threadIdx.x == 0) g_part5[k][blockIdx.x] = r;
        }
    }

    // ---- last-block finalize ----
    __shared__ bool is_last;
    if (threadIdx.x == 0) {
        __threadfence();                     // publish this block's partials
        unsigned c = atomicAdd(&g_count, 1u);
        is_last = (c == (unsigned)(NBLK - 1));
    }
    __syncthreads();
    if (!is_last) return;
    __threadfence();                         // acquire all blocks' partials

    float acc[NACC];
    #pragma unroll
    for (int k = 0; k < NACC; k++) {
        float a = 0.0f;
        for (int i = threadIdx.x; i < NBLK; i += NT)
            a += g_part5[k][i];              // coalesced
        acc[k] = a;
    }
    float tot[NACC];
    #pragma unroll
    for (int k = 0; k < NACC; k++) tot[k] = block_reduce(acc[k], sh);

    if (threadIdx.x == 0) {
        const float ALPHA = 0.3f, BETA = 0.7f, GAMMA = 1.33f, EPS = 1e-7f;
        float p1s  = tot[0];
        float i1   = tot[1];
        float c1   = tot[2];
        float csum = tot[3];
        float uds  = tot[4];

        float p0s = (float)NPIX - p1s;
        float c0  = (float)NPIX - c1;
        float i0  = (float)NPIX - c1 - p1s + i1;   // sum((1-cf)*(1-p1))

        float fp0 = p0s - i0;
        float fn0 = c0 - i0;
        float d0  = fmaxf(i0 + ALPHA * fp0 + BETA * fn0 + EPS, EPS);
        float loss0 = powf(1.0f - i0 / d0, GAMMA) * (c0 > 0.0f ? 1.0f : 0.0f);

        float fp1 = p1s - i1;
        float fn1 = c1 - i1;
        float d1  = fmaxf(i1 + ALPHA * fp1 + BETA * fn1 + EPS, EPS);
        float loss1 = powf(1.0f - i1 / d1, GAMMA) * (c1 > 0.0f ? 1.0f : 0.0f);

        float tversky = 0.5f * (loss0 + loss1);
        float elev    = (csum + uds) / fmaxf(csum, 1.0f);

        out[0] = tversky * elev;
        g_count = 0;   // reset for next graph replay
    }
}

extern "C" void kernel_launch(void* const* d_in, const int* in_sizes, int n_in,
                              void* d_out, int out_size)
{
    const float* pred = (const float*)d_in[0];   // (8,2,512,512) f32
    const float* hgt  = (const float*)d_in[1];   // (8,1,512,512) f32
    const int*   gt   = (const int*)  d_in[2];   // (8,1,512,512) i32
    float* out = (float*)d_out;

    elev_fused<<<NBLK, NT>>>(pred, hgt, gt, out);
}

// round 10
// speedup vs baseline: 1.0026x; 1.0026x over previous
#include <cuda_runtime.h>

// ElevationLoss: tversky(logits, gt) * elevation(softmax, heights, gt)
// B=8, C=2, H=W=512, gt in {0,1}. Strip-per-block smem kernel:
// block = 4 rows x 512 cols; 6 gt/h rows staged in smem as (A,B)=(2g-1,-A*h).

#define IMG_W 512
#define IMG_H 512
#define HW (IMG_H * IMG_W)        // 262144
#define NBATCH 8
#define NPIX (NBATCH * HW)        // 2097152
#define NT 256
#define NBLK 1024                 // 8 images x 128 strips (512/4 rows)
#define SW 516                    // padded smem row width (offset +2)
#define NACC 5

// SoA per-block partials: [Σp1, inter1, count1, comb_sum, ud_sum]
__device__ float g_part5[NACC][NBLK];
__device__ unsigned g_count = 0;               // reset by last block each launch
__device__ __align__(16) float g_zrowf[IMG_W]; // zero-initialized, never written
__device__ __align__(16) int   g_zrowi[IMG_W]; // zero-initialized, never written

__device__ __forceinline__ float block_reduce(float v, float* sh) {
    #pragma unroll
    for (int o = 16; o > 0; o >>= 1) v += __shfl_down_sync(0xffffffffu, v, o);
    int lane = threadIdx.x & 31;
    int w = threadIdx.x >> 5;
    __syncthreads();                 // protect sh reuse across calls
    if (lane == 0) sh[w] = v;
    __syncthreads();
    if (w == 0) {
        v = (lane < NT / 32) ? sh[lane] : 0.0f;
        #pragma unroll
        for (int o = 4; o > 0; o >>= 1) v += __shfl_down_sync(0xffffffffu, v, o);
    }
    return v;   // valid in thread 0
}

__global__ __launch_bounds__(NT) void elev_fused(
    const float* __restrict__ pred,   // (B,2,H,W)
    const float* __restrict__ hgt,    // (B,1,H,W)
    const int*   __restrict__ gt,     // (B,1,H,W)
    float* __restrict__ out)
{
    __shared__ float2 sm[6 * SW];    // rows y0-1 .. y0+4, padded +2 cols
    __shared__ float  shred[NT / 32];

    int tid = threadIdx.x;
    int bi  = blockIdx.x;
    int b     = bi >> 7;             // image
    int strip = bi & 127;
    int y0    = strip << 2;

    const float* pb = pred + ((size_t)b * 2) * HW;
    const float* hb = hgt + (size_t)b * HW;
    const int*   gb = gt  + (size_t)b * HW;

    // ---- logits prefetch (latency hidden under smem fill) ----
    int r0 = tid >> 6;               // row within strip (0..3)
    int c0 = tid & 63;               // base col; pixels c0 + 64*m
    int yy = y0 + r0;
    float l0[8], l1[8];
    {
        const float* lp = pb + (yy << 9);
        #pragma unroll
        for (int m = 0; m < 8; m++) {
            int c = c0 + (m << 6);
            l0[m] = lp[c];
            l1[m] = lp[HW + c];
        }
    }

    // ---- smem fill: 6 rows x 128 vec4 chunks = 768 tasks, 3 per thread ----
    #pragma unroll
    for (int i = 0; i < 3; i++) {
        int task = tid + (i << 8);
        int k = task >> 7;           // smem row 0..5
        int j = task & 127;          // vec4 chunk
        int y = y0 - 1 + k;
        bool v = (unsigned)y < (unsigned)IMG_H;
        const int*   gp = v ? (gb + (y << 9)) : g_zrowi;
        const float* hp = v ? (hb + (y << 9)) : g_zrowf;
        int4   g4 = ((const int4*)  gp)[j];
        float4 h4 = ((const float4*)hp)[j];
        float A0 = (float)(2 * g4.x - 1), A1 = (float)(2 * g4.y - 1);
        float A2 = (float)(2 * g4.z - 1), A3 = (float)(2 * g4.w - 1);
        float4 v0 = make_float4(A0, -A0 * h4.x, A1, -A1 * h4.y);
        float4 v1 = make_float4(A2, -A2 * h4.z, A3, -A3 * h4.w);
        float4* dst = (float4*)&sm[k * SW + 2 + (j << 2)];
        dst[0] = v0;
        dst[1] = v1;
    }
    if (tid < 12) {                  // halo cols: zero-pad -> g=0,h=0 -> (-1,0)
        int k = tid >> 1;
        sm[k * SW + ((tid & 1) ? 514 : 1)] = make_float2(-1.f, 0.f);
    }
    __syncthreads();

    // ---- compute: 8 pixels/thread, stride-64 cols (conflict-free LDS) ----
    float s_p1 = 0.f, s_i1 = 0.f, s_ud = 0.f, s_cb = 0.f;
    int c1i = 0;
    int base0 = r0 * SW + 2 + c0;    // smem row r0 = global row yy-1
    #pragma unroll
    for (int m = 0; m < 8; m++) {
        int s0 = base0 + (m << 6);
        float2 a0 = sm[s0 - 1],        a1 = sm[s0],        a2 = sm[s0 + 1];
        float2 b0 = sm[s0 + SW - 1],   b1 = sm[s0 + SW],   b2 = sm[s0 + SW + 1];
        float2 e0 = sm[s0 + 2*SW - 1], e1 = sm[s0 + 2*SW], e2 = sm[s0 + 2*SW + 1];

        float Ac = b1.x;
        float hc = -Ac * b1.y;       // exact: B = -A*h, A = ±1

        float t  = l1[m] - l0[m];
        float p1 = 1.0f / (1.0f + __expf(-t));
        s_p1 += p1;
        bool fl = (Ac > 0.f);        // center flood (g==1)
        if (fl) { s_i1 += p1; c1i++; }
        float u = (t > 0.f) ? p1 : p1 - 1.f;

        // neighbor passes iff A*hc + B <= 0  (== gt_sign*(h-hc) <= 0);
        // pass adds 1 to cb and -A (= gt_signed) to dd.
        float cb = 0.f, dd = 0.f;
        #pragma unroll
        for (int n = 0; n < 9; n++) {
            float2 X = (n == 0) ? a0 : (n == 1) ? a1 : (n == 2) ? a2 :
                       (n == 3) ? b0 : (n == 4) ? b1 : (n == 5) ? b2 :
                       (n == 6) ? e0 : (n == 7) ? e1 : e2;
            float mm = fmaf(X.x, hc, X.y);
            if (mm <= 0.f) { cb += 1.f; dd -= X.x; }
        }
        s_cb += cb;
        s_ud = fmaf(u, dd, s_ud);
    }

    // ---- per-block reduction (SoA partials) ----
    {
        float acc[NACC] = {s_p1, s_i1, (float)c1i, s_cb, s_ud};
        #pragma unroll
        for (int k = 0; k < NACC; k++) {
            float r = block_reduce(acc[k], shred);
            if (threadIdx.x == 0) g_part5[k][bi] = r;
        }
    }

    // ---- last-block finalize ----
    __shared__ bool is_last;
    if (tid == 0) {
        __threadfence();                     // publish this block's partials
        unsigned c = atomicAdd(&g_count, 1u);
        is_last = (c == (unsigned)(NBLK - 1));
    }
    __syncthreads();
    if (!is_last) return;
    __threadfence();                         // acquire all blocks' partials

    float acc[NACC];
    #pragma unroll
    for (int k = 0; k < NACC; k++) {
        float a = 0.0f;
        for (int i = tid; i < NBLK; i += NT)
            a += g_part5[k][i];              // coalesced
        acc[k] = a;
    }
    float tot[NACC];
    #pragma unroll
    for (int k = 0; k < NACC; k++) tot[k] = block_reduce(acc[k], shred);

    if (tid == 0) {
        const float ALPHA = 0.3f, BETA = 0.7f, GAMMA = 1.33f, EPS = 1e-7f;
        float p1s  = tot[0];
        float i1   = tot[1];
        float c1   = tot[2];
        float csum = tot[3];
        float uds  = tot[4];

        float p0s = (float)NPIX - p1s;
        float c0f = (float)NPIX - c1;
        float i0  = (float)NPIX - c1 - p1s + i1;   // sum((1-cf)*(1-p1))

        float fp0 = p0s - i0;
        float fn0 = c0f - i0;
        float d0  = fmaxf(i0 + ALPHA * fp0 + BETA * fn0 + EPS, EPS);
        float loss0 = powf(1.0f - i0 / d0, GAMMA) * (c0f > 0.0f ? 1.0f : 0.0f);

        float fp1 = p1s - i1;
        float fn1 = c1 - i1;
        float d1  = fmaxf(i1 + ALPHA * fp1 + BETA * fn1 + EPS, EPS);
        float loss1 = powf(1.0f - i1 / d1, GAMMA) * (c1 > 0.0f ? 1.0f : 0.0f);

        float tversky = 0.5f * (loss0 + loss1);
        float elev    = (csum + uds) / fmaxf(csum, 1.0f);

        out[0] = tversky * elev;
        g_count = 0;   // reset for next graph replay
    }
}

extern "C" void kernel_launch(void* const* d_in, const int* in_sizes, int n_in,
                              void* d_out, int out_size)
{
    const float* pred = (const float*)d_in[0];   // (8,2,512,512) f32
    const float* hgt  = (const float*)d_in[1];   // (8,1,512,512) f32
    const int*   gt   = (const int*)  d_in[2];   // (8,1,512,512) i32
    float* out = (float*)d_out;

    elev_fused<<<NBLK, NT>>>(pred, hgt, gt, out);
}

// round 12
// speedup vs baseline: 1.0922x; 1.0894x over previous
#include <cuda_runtime.h>

// ElevationLoss: tversky(logits, gt) * elevation(softmax, heights, gt)
// B=8, C=2, H=W=512, gt in {0,1}. Strip kernel: block = 8 rows x 256 cols.
// Thread = 1 col x 8 rows, rolling 3x3 register window over smem rows.
// Smem cell (A,B) = (2g-1, -A*h); enc = 1 + A/16 packs (count, sumA) per test.

#define IMG_W 512
#define IMG_H 512
#define HW (IMG_H * IMG_W)        // 262144
#define NBATCH 8
#define NPIX (NBATCH * HW)        // 2097152
#define NT 256
#define NBLK 1024                 // 8 images x 64 strips x 2 col-halves
#define SW2 260                   // padded smem row width (cells)
#define NACC 5

// SoA per-block partials: [Σp1, inter1, count1, comb_sum, ud_sum]
__device__ float g_part5[NACC][NBLK];
__device__ unsigned g_count = 0;               // reset by last block each launch
__device__ __align__(16) float g_zrowf[IMG_W]; // zero-initialized, never written
__device__ __align__(16) int   g_zrowi[IMG_W]; // zero-initialized, never written

__device__ __forceinline__ float block_reduce(float v, float* sh) {
    #pragma unroll
    for (int o = 16; o > 0; o >>= 1) v += __shfl_down_sync(0xffffffffu, v, o);
    int lane = threadIdx.x & 31;
    int w = threadIdx.x >> 5;
    __syncthreads();                 // protect sh reuse across calls
    if (lane == 0) sh[w] = v;
    __syncthreads();
    if (w == 0) {
        v = (lane < NT / 32) ? sh[lane] : 0.0f;
        #pragma unroll
        for (int o = 4; o > 0; o >>= 1) v += __shfl_down_sync(0xffffffffu, v, o);
    }
    return v;   // valid in thread 0
}

__global__ __launch_bounds__(NT) void elev_fused(
    const float* __restrict__ pred,   // (B,2,H,W)
    const float* __restrict__ hgt,    // (B,1,H,W)
    const int*   __restrict__ gt,     // (B,1,H,W)
    float* __restrict__ out)
{
    __shared__ float2 sm[10 * SW2];  // rows y0-1 .. y0+8, cols x0-1 .. x0+256
    __shared__ float  shred[NT / 32];

    int tid = threadIdx.x;
    int bi  = blockIdx.x;
    int b     = bi >> 7;             // image
    int rr    = bi & 127;
    int strip = rr >> 1;             // 64 strips of 8 rows
    int half  = rr & 1;              // 2 col-halves of 256
    int y0    = strip << 3;
    int x0    = half << 8;

    const float* pb = pred + ((size_t)b * 2) * HW;
    const float* hb = hgt + (size_t)b * HW;
    const int*   gb = gt  + (size_t)b * HW;

    // ---- logit prefetch: t[p] = l1 - l0 for the thread's column ----
    float t[8];
    {
        const float* lp = pb + (y0 << 9) + x0 + tid;
        #pragma unroll
        for (int p = 0; p < 8; p++)
            t[p] = lp[HW + (p << 9)] - lp[p << 9];
    }

    // ---- smem fill: 10 rows x 64 vec4 chunks = 640 tasks ----
    #pragma unroll
    for (int i = 0; i < 3; i++) {
        int task = tid + (i << 8);
        if (task < 640) {
            int k = task >> 6;       // smem row 0..9
            int j = task & 63;       // vec4 chunk (4 cols)
            int y = y0 - 1 + k;
            bool v = (unsigned)y < (unsigned)IMG_H;
            const int*   gp = v ? (gb + (y << 9) + x0) : (g_zrowi + x0);
            const float* hp = v ? (hb + (y << 9) + x0) : (g_zrowf + x0);
            int4   g4 = ((const int4*)  gp)[j];
            float4 h4 = ((const float4*)hp)[j];
            float A0 = (float)(2 * g4.x - 1), A1 = (float)(2 * g4.y - 1);
            float A2 = (float)(2 * g4.z - 1), A3 = (float)(2 * g4.w - 1);
            float4* dst = (float4*)&sm[k * SW2 + 2 + (j << 2)];
            dst[0] = make_float4(A0, -A0 * h4.x, A1, -A1 * h4.y);
            dst[1] = make_float4(A2, -A2 * h4.z, A3, -A3 * h4.w);
        }
    }
    if (tid < 20) {                  // halo cols (x0-1 at sc=1, x0+256 at sc=258)
        int k    = tid >> 1;
        int side = tid & 1;
        int xcol = side ? (x0 + 256) : (x0 - 1);
        int sc   = side ? 258 : 1;
        int y    = y0 - 1 + k;
        bool vy = (unsigned)y < (unsigned)IMG_H;
        bool vx = (unsigned)xcol < (unsigned)IMG_W;
        const int*   gp = vy ? (gb + (y << 9)) : g_zrowi;
        const float* hp = vy ? (hb + (y << 9)) : g_zrowf;
        int   g = vx ? gp[xcol] : 0;
        float h = vx ? hp[xcol] : 0.f;
        float A = (float)(2 * g - 1);
        sm[k * SW2 + sc] = make_float2(A, -A * h);
    }
    __syncthreads();

    // ---- compute: 8 pixels down the column, rolling 3x3 window ----
    float s_p1 = 0.f, s_i1 = 0.f, s_cb8 = 0.f, s_udr = 0.f, s_uac = 0.f;
    int c1i = 0;

    const float2* col = sm + tid + 1;    // cells at +0,+1,+2 = left,center,right
    float2 X0[3], X1[3];
    float  e0[3], e1[3];
    #pragma unroll
    for (int j = 0; j < 3; j++) {
        X0[j] = col[j];                  // smem row 0
        X1[j] = col[SW2 + j];            // smem row 1
        e0[j] = fmaf(0.0625f, X0[j].x, 1.0f);
        e1[j] = fmaf(0.0625f, X1[j].x, 1.0f);
    }

    #pragma unroll
    for (int p = 0; p < 8; p++) {
        float2 N[3];
        float  e2[3];
        #pragma unroll
        for (int j = 0; j < 3; j++) {
            N[j]  = col[(p + 2) * SW2 + j];
            e2[j] = fmaf(0.0625f, N[j].x, 1.0f);
        }

        float Ac = X1[1].x;
        float hc = -Ac * X1[1].y;        // exact: B = -A*h, A = ±1

        // 8 neighbor tests (self excluded): pass iff A*hc + B <= 0.
        // Pass adds enc = 1 + A/16 into acc (sign-bit mask, branchless).
        float acc = 0.f;
        #pragma unroll
        for (int j = 0; j < 3; j++) {
            float m0 = fmaf(X0[j].x, hc, X0[j].y);
            acc += __int_as_float((__float_as_int(m0) >> 31) & __float_as_int(e0[j]));
            float m2 = fmaf(N[j].x, hc, N[j].y);
            acc += __int_as_float((__float_as_int(m2) >> 31) & __float_as_int(e2[j]));
        }
        {
            float ml = fmaf(X1[0].x, hc, X1[0].y);
            acc += __int_as_float((__float_as_int(ml) >> 31) & __float_as_int(e1[0]));
            float mr = fmaf(X1[2].x, hc, X1[2].y);
            acc += __int_as_float((__float_as_int(mr) >> 31) & __float_as_int(e1[2]));
        }

        // softmax + unified pred + tversky partials
        float p1 = 1.0f / (1.0f + __expf(-t[p]));
        s_p1 += p1;
        if (Ac > 0.f) { s_i1 += p1; c1i++; }
        float u = (t[p] > 0.f) ? p1 : p1 - 1.f;

        // decode packed acc: cb8 = rintf(acc), sumA/16 = acc - cb8
        float cbf = rintf(acc);
        s_cb8 += cbf;
        s_udr = fmaf(u, acc - cbf, s_udr);
        s_uac = fmaf(u, Ac, s_uac);

        // rotate window
        #pragma unroll
        for (int j = 0; j < 3; j++) {
            X0[j] = X1[j]; e0[j] = e1[j];
            X1[j] = N[j];  e1[j] = e2[j];
        }
    }

    // ---- per-block reduction (SoA partials) ----
    // csum: +1 per pixel for self (8/thread). uds = -16*s_udr - s_uac
    // (pass adds -A to dd; self adds -Ac).
    {
        float acc5[NACC] = {s_p1, s_i1, (float)c1i,
                            s_cb8 + 8.0f, -16.0f * s_udr - s_uac};
        #pragma unroll
        for (int k = 0; k < NACC; k++) {
            float r = block_reduce(acc5[k], shred);
            if (threadIdx.x == 0) g_part5[k][bi] = r;
        }
    }

    // ---- last-block finalize ----
    __shared__ bool is_last;
    if (tid == 0) {
        __threadfence();                     // publish this block's partials
        unsigned c = atomicAdd(&g_count, 1u);
        is_last = (c == (unsigned)(NBLK - 1));
    }
    __syncthreads();
    if (!is_last) return;
    __threadfence();                         // acquire all blocks' partials

    float acc[NACC];
    #pragma unroll
    for (int k = 0; k < NACC; k++) {
        float a = 0.0f;
        for (int i = tid; i < NBLK; i += NT)
            a += g_part5[k][i];              // coalesced
        acc[k] = a;
    }
    float tot[NACC];
    #pragma unroll
    for (int k = 0; k < NACC; k++) tot[k] = block_reduce(acc[k], shred);

    if (tid == 0) {
        const float ALPHA = 0.3f, BETA = 0.7f, GAMMA = 1.33f, EPS = 1e-7f;
        float p1s  = tot[0];
        float i1   = tot[1];
        float c1   = tot[2];
        float csum = tot[3];
        float uds  = tot[4];

        float p0s = (float)NPIX - p1s;
        float c0f = (float)NPIX - c1;
        float i0  = (float)NPIX - c1 - p1s + i1;   // sum((1-cf)*(1-p1))

        float fp0 = p0s - i0;
        float fn0 = c0f - i0;
        float d0  = fmaxf(i0 + ALPHA * fp0 + BETA * fn0 + EPS, EPS);
        float loss0 = powf(1.0f - i0 / d0, GAMMA) * (c0f > 0.0f ? 1.0f : 0.0f);

        float fp1 = p1s - i1;
        float fn1 = c1 - i1;
        float d1  = fmaxf(i1 + ALPHA * fp1 + BETA * fn1 + EPS, EPS);
        float loss1 = powf(1.0f - i1 / d1, GAMMA) * (c1 > 0.0f ? 1.0f : 0.0f);

        float tversky = 0.5f * (loss0 + loss1);
        float elev    = (csum + uds) / fmaxf(csum, 1.0f);

        out[0] = tversky * elev;
        g_count = 0;   // reset for next graph replay
    }
}

extern "C" void kernel_launch(void* const* d_in, const int* in_sizes, int n_in,
                              void* d_out, int out_size)
{
    const float* pred = (const float*)d_in[0];   // (8,2,512,512) f32
    const float* hgt  = (const float*)d_in[1];   // (8,1,512,512) f32
    const int*   gt   = (const int*)  d_in[2];   // (8,1,512,512) i32
    float* out = (float*)d_out;

    elev_fused<<<NBLK, NT>>>(pred, hgt, gt, out);
}